// round 5
// baseline (speedup 1.0000x reference)
#include <cuda_runtime.h>
#include <math.h>
#include <stdint.h>

#define O_DIM 1024
#define D_DIM 1024
#define E_NUM 16
#define TOPK  4
#define H_DIM 2048
#define A_DIM 64
#define NPAIR (O_DIM * TOPK)
#define FLT_MIN_NORM 1.17549435e-38f

// ---------------- scratch (static device memory; no allocs) ----------------
__device__ int   g_topk_idx[NPAIR];
__device__ float g_topk_gate[NPAIR];
__device__ float g_importance[O_DIM];
__device__ float g_load[O_DIM];
__device__ int   g_base[E_NUM + 1];
__device__ int   g_rows_sorted[NPAIR];
__device__ int   g_pair_of[NPAIR];
__device__ float g_h[NPAIR * H_DIM];   // 32 MB relu(fc1) activations
__device__ float g_z[NPAIR * A_DIM];   // 1 MB  fc2 outputs per pair

// ---------------- helpers ----------------
__device__ __forceinline__ unsigned f2tf(float x) {
    unsigned u;
    asm("cvt.rna.tf32.f32 %0, %1;" : "=r"(u) : "f"(x));
    return u;
}

__device__ __forceinline__ void mma_tf32(float c[4], unsigned a0, unsigned a1,
                                         unsigned a2, unsigned a3,
                                         unsigned b0, unsigned b1) {
    asm volatile(
        "mma.sync.aligned.m16n8k8.row.col.f32.tf32.tf32.f32 "
        "{%0,%1,%2,%3}, {%4,%5,%6,%7}, {%8,%9}, {%0,%1,%2,%3};\n"
        : "+f"(c[0]), "+f"(c[1]), "+f"(c[2]), "+f"(c[3])
        : "r"(a0), "r"(a1), "r"(a2), "r"(a3), "r"(b0), "r"(b1));
}

// ---------------- K1: gating ----------------
__global__ __launch_bounds__(256) void gate_kernel(const float* __restrict__ obs,
                                                   const float* __restrict__ wg) {
    int o = blockIdx.x;
    int tid = threadIdx.x;
    const float* wrow = wg + (size_t)o * D_DIM * E_NUM;
    const float* orow = obs + (size_t)o * D_DIM;

    float acc[E_NUM];
#pragma unroll
    for (int i = 0; i < E_NUM; i++) acc[i] = 0.f;

    for (int d = tid; d < D_DIM; d += 256) {
        float x = orow[d];
        const float4* p = reinterpret_cast<const float4*>(wrow + (size_t)d * E_NUM);
        float4 v0 = p[0], v1 = p[1], v2 = p[2], v3 = p[3];
        acc[0]  += x * v0.x; acc[1]  += x * v0.y; acc[2]  += x * v0.z; acc[3]  += x * v0.w;
        acc[4]  += x * v1.x; acc[5]  += x * v1.y; acc[6]  += x * v1.z; acc[7]  += x * v1.w;
        acc[8]  += x * v2.x; acc[9]  += x * v2.y; acc[10] += x * v2.z; acc[11] += x * v2.w;
        acc[12] += x * v3.x; acc[13] += x * v3.y; acc[14] += x * v3.z; acc[15] += x * v3.w;
    }
#pragma unroll
    for (int i = 0; i < E_NUM; i++) {
#pragma unroll
        for (int off = 16; off; off >>= 1)
            acc[i] += __shfl_xor_sync(0xffffffffu, acc[i], off);
    }
    __shared__ float s[8][E_NUM];
    int warp = tid >> 5, lane = tid & 31;
    if (lane == 0) {
#pragma unroll
        for (int i = 0; i < E_NUM; i++) s[warp][i] = acc[i];
    }
    __syncthreads();
    if (tid == 0) {
        float logit[E_NUM];
        for (int e = 0; e < E_NUM; e++) {
            float t = 0.f;
            for (int w = 0; w < 8; w++) t += s[w][e];
            logit[e] = t;
        }
        bool taken[E_NUM];
        for (int e = 0; e < E_NUM; e++) taken[e] = false;
        int idx[TOPK]; float val[TOPK];
        for (int k = 0; k < TOPK; k++) {
            float best = -3.4e38f; int bi = 0;
            for (int e = 0; e < E_NUM; e++)
                if (!taken[e] && logit[e] > best) { best = logit[e]; bi = e; }
            taken[bi] = true; idx[k] = bi; val[k] = best;
        }
        float m = val[0];
        float ex[TOPK]; float se = 0.f;
        for (int k = 0; k < TOPK; k++) { ex[k] = expf(val[k] - m); se += ex[k]; }
        float gates[E_NUM];
        for (int e = 0; e < E_NUM; e++) gates[e] = 0.f;
        for (int k = 0; k < TOPK; k++) gates[idx[k]] = ex[k] / se;
        float imp = 0.f; int ldc = 0;
        for (int e = 0; e < E_NUM; e++) { imp += gates[e]; ldc += (gates[e] > 0.f); }
        for (int k = 0; k < TOPK; k++) {
            g_topk_idx[o * TOPK + k]  = idx[k];
            g_topk_gate[o * TOPK + k] = gates[idx[k]];
        }
        g_importance[o] = imp;
        g_load[o] = (float)ldc;
    }
}

// ---------------- K2: deterministic binning ----------------
__global__ __launch_bounds__(512) void bin_kernel() {
    int tid = threadIdx.x;
    int warp = tid >> 5, lane = tid & 31;
    int e = warp;
    __shared__ int scnt[E_NUM];
    __shared__ int sbase[E_NUM + 1];

    int cnt = 0;
    for (int base = 0; base < O_DIM; base += 32) {
        int r = base + lane;
        bool f = (g_topk_idx[r * 4 + 0] == e) || (g_topk_idx[r * 4 + 1] == e) ||
                 (g_topk_idx[r * 4 + 2] == e) || (g_topk_idx[r * 4 + 3] == e);
        unsigned m = __ballot_sync(0xffffffffu, f);
        cnt += __popc(m);
    }
    if (lane == 0) scnt[e] = cnt;
    __syncthreads();
    if (tid == 0) {
        int s = 0;
        for (int q = 0; q < E_NUM; q++) { sbase[q] = s; s += scnt[q]; }
        sbase[E_NUM] = s;
    }
    __syncthreads();
    if (tid < E_NUM + 1) g_base[tid] = sbase[tid];

    int off = sbase[e];
    for (int base = 0; base < O_DIM; base += 32) {
        int r = base + lane;
        int j = -1;
        if      (g_topk_idx[r * 4 + 0] == e) j = 0;
        else if (g_topk_idx[r * 4 + 1] == e) j = 1;
        else if (g_topk_idx[r * 4 + 2] == e) j = 2;
        else if (g_topk_idx[r * 4 + 3] == e) j = 3;
        bool f = (j >= 0);
        unsigned m = __ballot_sync(0xffffffffu, f);
        int pos = off + __popc(m & ((1u << lane) - 1u));
        if (f) {
            g_rows_sorted[pos] = r;
            g_pair_of[r * 4 + j] = pos;
        }
        off += __popc(m);
    }
}

// ---------------- K3: loss (two-pass variance, ddof=1) ----------------
__global__ __launch_bounds__(1024) void loss_kernel(float* __restrict__ out) {
    int tid = threadIdx.x;
    __shared__ float sh[32];
    __shared__ float bc;
    float imp = g_importance[tid];
    float ld  = g_load[tid];

    auto reduceSum = [&](float v) -> float {
#pragma unroll
        for (int o2 = 16; o2; o2 >>= 1) v += __shfl_xor_sync(0xffffffffu, v, o2);
        if ((tid & 31) == 0) sh[tid >> 5] = v;
        __syncthreads();
        if (tid < 32) {
            float r = sh[tid];
#pragma unroll
            for (int o2 = 16; o2; o2 >>= 1) r += __shfl_xor_sync(0xffffffffu, r, o2);
            if (tid == 0) bc = r;
        }
        __syncthreads();
        float r = bc;
        __syncthreads();
        return r;
    };

    float si  = reduceSum(imp);
    float mi  = si / (float)O_DIM;
    float di  = imp - mi;
    float ssi = reduceSum(di * di);
    float sl  = reduceSum(ld);
    float ml  = sl / (float)O_DIM;
    float dl  = ld - ml;
    float ssl = reduceSum(dl * dl);
    if (tid == 0) {
        float vi = ssi / (float)(O_DIM - 1);
        float vl = ssl / (float)(O_DIM - 1);
        float loss = (vi / (mi * mi + 1e-10f) + vl / (ml * ml + 1e-10f)) * 0.01f;
        out[3 * O_DIM * A_DIM] = loss;
    }
}

// ---------------- K4: action head (float4 streaming; FTZ-emulated tail) ----
__global__ __launch_bounds__(512) void action_kernel(const float* __restrict__ obs,
                                                     const float* __restrict__ lastw,
                                                     const float* __restrict__ lastb,
                                                     float* __restrict__ out) {
    int o = blockIdx.x;
    int tid = threadIdx.x;
    int a4 = (tid & 15) * 4;     // column group: 0,4,...,60
    int chunk = tid >> 4;        // 0..31, each covers 32 d

    __shared__ float obsS[D_DIM];
    obsS[tid]       = obs[(size_t)o * D_DIM + tid];
    obsS[tid + 512] = obs[(size_t)o * D_DIM + tid + 512];
    __syncthreads();

    const float* lw = lastw + (size_t)o * D_DIM * A_DIM + (size_t)chunk * 32 * A_DIM + a4;
    float ax = 0.f, ay = 0.f, az = 0.f, aw = 0.f;
#pragma unroll 8
    for (int d = 0; d < 32; d++) {
        float4 w = *reinterpret_cast<const float4*>(lw + (size_t)d * A_DIM);
        float x = obsS[chunk * 32 + d];
        ax += x * w.x; ay += x * w.y; az += x * w.z; aw += x * w.w;
    }

    __shared__ float red[32][A_DIM];
    red[chunk][a4 + 0] = ax;
    red[chunk][a4 + 1] = ay;
    red[chunk][a4 + 2] = az;
    red[chunk][a4 + 3] = aw;
    __syncthreads();

    __shared__ float muS[A_DIM];
    __shared__ float eS[A_DIM];
    if (tid < A_DIM) {
        float m = 0.f;
        for (int c = 0; c < 32; c++) m += red[c][tid];
        muS[tid] = m + lastb[o * A_DIM + tid];
    }
    __syncthreads();
    if (tid < A_DIM) {
        float mx = muS[0];
        for (int i = 1; i < A_DIM; i++) mx = fmaxf(mx, muS[i]);
        float t  = muS[tid] - mx;
        float ef = expf(t);
        if (ef < FLT_MIN_NORM) ef = 0.f;          // FTZ: flush denormal exp result
        eS[tid] = ef;
    }
    __syncthreads();
    if (tid < A_DIM) {
        float ssum = 0.f;
        for (int i = 0; i < A_DIM; i++) ssum += eS[i];
        float p = eS[tid] / ssum;
        if (p < FLT_MIN_NORM) p = 0.f;            // FTZ: flush denormal quotient
        out[(size_t)o * A_DIM + tid] = p;
        float lp = (p == 0.f) ? logf(1e-8f) : logf(p);
        out[(size_t)O_DIM * A_DIM + o * A_DIM + tid] = lp;
    }
}

// ---------------- K5: fc1 grouped GEMM (legacy tf32 mma, pipelined) --------
// CTA 128M x 128N, 8 warps (2M x 4N), warp tile 64x32.
// K-chunk 16, double-buffered smem + register-staged LDG prefetch.
// Static smem 37.9 KB -> 2 CTAs/SM (__launch_bounds__(256, 2)).
__global__ __launch_bounds__(256, 2) void expert_fc1_kernel(const float* __restrict__ obs,
                                                            const float* __restrict__ w1,
                                                            const float* __restrict__ b1) {
    int e = blockIdx.z, mt = blockIdx.y, nt = blockIdx.x;
    int pb = g_base[e];
    int ne = g_base[e + 1] - pb;
    int m0 = mt * 128;
    if (m0 >= ne) return;

    __shared__ unsigned As[2][128][20];   // [buf][row][k], stride 20 (conflict-free frags)
    __shared__ unsigned Bs[2][16][136];   // [buf][k][n],   stride 136 (8k+n distinct banks)

    int tid = threadIdx.x;
    int lane = tid & 31, warp = tid >> 5;
    int wm = warp >> 2, wn = warp & 3;    // 2 x 4 warp grid

    // fixed per-thread load coordinates
    int arow  = tid >> 1;                 // 0..127
    int akoff = (tid & 1) * 8;            // 0 or 8
    int mi = m0 + arow;
    int rowidx = g_rows_sorted[pb + (mi < ne ? mi : 0)];
    const float* aptr = obs + (size_t)rowidx * D_DIM + akoff;

    int bk = tid >> 4;                    // 0..15
    int bn = (tid & 15) * 8;              // 0..120
    const float* w1e = w1 + (size_t)e * D_DIM * H_DIM + (size_t)nt * 128;
    const float* bptr = w1e + (size_t)bk * H_DIM + bn;

    float c[4][4][4];
#pragma unroll
    for (int i = 0; i < 4; i++)
#pragma unroll
        for (int j = 0; j < 4; j++)
#pragma unroll
            for (int q = 0; q < 4; q++) c[i][j][q] = 0.f;

    float4 sa0, sa1, sb0, sb1;

    // prologue: load chunk 0, store to buf 0
    sa0 = *reinterpret_cast<const float4*>(aptr);
    sa1 = *reinterpret_cast<const float4*>(aptr + 4);
    sb0 = *reinterpret_cast<const float4*>(bptr);
    sb1 = *reinterpret_cast<const float4*>(bptr + 4);
    {
        uint4 u0 = {f2tf(sa0.x), f2tf(sa0.y), f2tf(sa0.z), f2tf(sa0.w)};
        uint4 u1 = {f2tf(sa1.x), f2tf(sa1.y), f2tf(sa1.z), f2tf(sa1.w)};
        *reinterpret_cast<uint4*>(&As[0][arow][akoff])     = u0;
        *reinterpret_cast<uint4*>(&As[0][arow][akoff + 4]) = u1;
        uint4 v0 = {f2tf(sb0.x), f2tf(sb0.y), f2tf(sb0.z), f2tf(sb0.w)};
        uint4 v1 = {f2tf(sb1.x), f2tf(sb1.y), f2tf(sb1.z), f2tf(sb1.w)};
        *reinterpret_cast<uint4*>(&Bs[0][bk][bn])     = v0;
        *reinterpret_cast<uint4*>(&Bs[0][bk][bn + 4]) = v1;
    }
    __syncthreads();

    for (int ch = 0; ch < 64; ch++) {
        int cur = ch & 1;
        // prefetch next chunk into registers (hides DRAM latency behind MMAs)
        if (ch < 63) {
            const float* ap = aptr + (ch + 1) * 16;
            sa0 = *reinterpret_cast<const float4*>(ap);
            sa1 = *reinterpret_cast<const float4*>(ap + 4);
            const float* bp = bptr + (size_t)(ch + 1) * 16 * H_DIM;
            sb0 = *reinterpret_cast<const float4*>(bp);
            sb1 = *reinterpret_cast<const float4*>(bp + 4);
        }
        // MMA over current buffer: 2 k8 steps x (4m x 4n) tiles
#pragma unroll
        for (int ks = 0; ks < 2; ks++) {
            int k8 = ks * 8;
            unsigned af[4][4], bf[4][2];
#pragma unroll
            for (int i = 0; i < 4; i++) {
                int r0 = wm * 64 + i * 16 + (lane >> 2);
                int kk = k8 + (lane & 3);
                af[i][0] = As[cur][r0][kk];
                af[i][1] = As[cur][r0 + 8][kk];
                af[i][2] = As[cur][r0][kk + 4];
                af[i][3] = As[cur][r0 + 8][kk + 4];
            }
#pragma unroll
            for (int j = 0; j < 4; j++) {
                int col = wn * 32 + j * 8 + (lane >> 2);
                bf[j][0] = Bs[cur][k8 + (lane & 3)][col];
                bf[j][1] = Bs[cur][k8 + (lane & 3) + 4][col];
            }
#pragma unroll
            for (int i = 0; i < 4; i++)
#pragma unroll
                for (int j = 0; j < 4; j++)
                    mma_tf32(c[i][j], af[i][0], af[i][1], af[i][2], af[i][3],
                             bf[j][0], bf[j][1]);
        }
        if (ch < 63) {
            __syncthreads();   // all warps done reading buf cur^1 (their iter ch-1)
            int nxt = cur ^ 1;
            uint4 u0 = {f2tf(sa0.x), f2tf(sa0.y), f2tf(sa0.z), f2tf(sa0.w)};
            uint4 u1 = {f2tf(sa1.x), f2tf(sa1.y), f2tf(sa1.z), f2tf(sa1.w)};
            *reinterpret_cast<uint4*>(&As[nxt][arow][akoff])     = u0;
            *reinterpret_cast<uint4*>(&As[nxt][arow][akoff + 4]) = u1;
            uint4 v0 = {f2tf(sb0.x), f2tf(sb0.y), f2tf(sb0.z), f2tf(sb0.w)};
            uint4 v1 = {f2tf(sb1.x), f2tf(sb1.y), f2tf(sb1.z), f2tf(sb1.w)};
            *reinterpret_cast<uint4*>(&Bs[nxt][bk][bn])     = v0;
            *reinterpret_cast<uint4*>(&Bs[nxt][bk][bn + 4]) = v1;
            __syncthreads();
        }
    }

    // epilogue: bias + relu, write to g_h
    const float* b1e = b1 + e * H_DIM + nt * 128;
#pragma unroll
    for (int i = 0; i < 4; i++) {
        int r0 = m0 + wm * 64 + i * 16 + (lane >> 2);
#pragma unroll
        for (int j = 0; j < 4; j++) {
            int cc = wn * 32 + j * 8 + 2 * (lane & 3);
            float bv0 = b1e[cc], bv1 = b1e[cc + 1];
            if (r0 < ne) {
                float* dst = g_h + (size_t)(pb + r0) * H_DIM + nt * 128 + cc;
                dst[0] = fmaxf(c[i][j][0] + bv0, 0.f);
                dst[1] = fmaxf(c[i][j][1] + bv1, 0.f);
            }
            if (r0 + 8 < ne) {
                float* dst = g_h + (size_t)(pb + r0 + 8) * H_DIM + nt * 128 + cc;
                dst[0] = fmaxf(c[i][j][2] + bv0, 0.f);
                dst[1] = fmaxf(c[i][j][3] + bv1, 0.f);
            }
        }
    }
}

// ---------------- K6: grouped GEMM fc2 (h @ w2[e]) ----------------
__global__ __launch_bounds__(256) void expert_fc2_kernel(const float* __restrict__ w2) {
    int e = blockIdx.z, mt = blockIdx.y;
    int pb = g_base[e];
    int ne = g_base[e + 1] - pb;
    int m0 = mt * 64;
    if (m0 >= ne) return;

    __shared__ unsigned As[64][40];
    __shared__ unsigned Bs[32][72];

    int tid = threadIdx.x;
    int lane = tid & 31, warp = tid >> 5;
    int wm = warp >> 2, wn = warp & 3;

    float c[2][2][4];
#pragma unroll
    for (int i = 0; i < 2; i++)
#pragma unroll
        for (int j = 0; j < 2; j++)
#pragma unroll
            for (int q = 0; q < 4; q++) c[i][j][q] = 0.f;

    const float* w2e = w2 + (size_t)e * H_DIM * A_DIM;

    for (int kb = 0; kb < H_DIM; kb += 32) {
#pragma unroll
        for (int i = 0; i < 2; i++) {
            int v = tid + i * 256;
            int r = v >> 3, seg = v & 7;
            int row = pb + m0 + r;
            if (row > NPAIR - 1) row = NPAIR - 1;
            const float4* src = reinterpret_cast<const float4*>(
                g_h + (size_t)row * H_DIM + kb + seg * 4);
            float4 f = *src;
            As[r][seg * 4 + 0] = f2tf(f.x);
            As[r][seg * 4 + 1] = f2tf(f.y);
            As[r][seg * 4 + 2] = f2tf(f.z);
            As[r][seg * 4 + 3] = f2tf(f.w);
        }
#pragma unroll
        for (int i = 0; i < 2; i++) {
            int v = tid + i * 256;
            int k = v >> 4, seg = v & 15;
            const float4* src = reinterpret_cast<const float4*>(
                w2e + (size_t)(kb + k) * A_DIM + seg * 4);
            float4 f = *src;
            Bs[k][seg * 4 + 0] = f2tf(f.x);
            Bs[k][seg * 4 + 1] = f2tf(f.y);
            Bs[k][seg * 4 + 2] = f2tf(f.z);
            Bs[k][seg * 4 + 3] = f2tf(f.w);
        }
        __syncthreads();
#pragma unroll
        for (int ks = 0; ks < 4; ks++) {
            int k8 = ks * 8;
            unsigned af[2][4], bf[2][2];
#pragma unroll
            for (int i = 0; i < 2; i++) {
                int r0 = wm * 32 + i * 16 + (lane >> 2);
                int kk = k8 + (lane & 3);
                af[i][0] = As[r0][kk];
                af[i][1] = As[r0 + 8][kk];
                af[i][2] = As[r0][kk + 4];
                af[i][3] = As[r0 + 8][kk + 4];
            }
#pragma unroll
            for (int j = 0; j < 2; j++) {
                int col = wn * 16 + j * 8 + (lane >> 2);
                bf[j][0] = Bs[k8 + (lane & 3)][col];
                bf[j][1] = Bs[k8 + (lane & 3) + 4][col];
            }
#pragma unroll
            for (int i = 0; i < 2; i++)
#pragma unroll
                for (int j = 0; j < 2; j++)
                    mma_tf32(c[i][j], af[i][0], af[i][1], af[i][2], af[i][3],
                             bf[j][0], bf[j][1]);
        }
        __syncthreads();
    }

#pragma unroll
    for (int i = 0; i < 2; i++) {
        int r0 = m0 + wm * 32 + i * 16 + (lane >> 2);
#pragma unroll
        for (int j = 0; j < 2; j++) {
            int c0 = wn * 16 + j * 8 + 2 * (lane & 3);
            if (r0 < ne) {
                float* dst = g_z + (size_t)(pb + r0) * A_DIM + c0;
                dst[0] = c[i][j][0];
                dst[1] = c[i][j][1];
            }
            if (r0 + 8 < ne) {
                float* dst = g_z + (size_t)(pb + r0 + 8) * A_DIM + c0;
                dst[0] = c[i][j][2];
                dst[1] = c[i][j][3];
            }
        }
    }
}

// ---------------- K7: combine ----------------
__global__ __launch_bounds__(256) void combine_kernel(const float* __restrict__ b2,
                                                      float* __restrict__ out) {
    int i = blockIdx.x * blockDim.x + threadIdx.x;
    if (i >= O_DIM * A_DIM) return;
    int o = i >> 6, a = i & 63;
    float y = 0.f;
#pragma unroll
    for (int j = 0; j < TOPK; j++) {
        int eidx = g_topk_idx[o * TOPK + j];
        float g  = g_topk_gate[o * TOPK + j];
        int p    = g_pair_of[o * TOPK + j];
        y += g * (g_z[(size_t)p * A_DIM + a] + b2[eidx * A_DIM + a]);
    }
    out[2 * O_DIM * A_DIM + i] = y;
}

// ---------------- launch ----------------------------------------------------
extern "C" void kernel_launch(void* const* d_in, const int* in_sizes, int n_in,
                              void* d_out, int out_size) {
    const float* obs   = (const float*)d_in[0];
    const float* wgate = (const float*)d_in[1];
    const float* w1    = (const float*)d_in[2];
    const float* b1    = (const float*)d_in[3];
    const float* w2    = (const float*)d_in[4];
    const float* b2    = (const float*)d_in[5];
    const float* lastw = (const float*)d_in[6];
    const float* lastb = (const float*)d_in[7];
    float* out = (float*)d_out;

    gate_kernel<<<O_DIM, 256>>>(obs, wgate);
    bin_kernel<<<1, 512>>>();
    loss_kernel<<<1, 1024>>>(out);
    action_kernel<<<O_DIM, 512>>>(obs, lastw, lastb, out);
    expert_fc1_kernel<<<dim3(16, 8, 16), 256>>>(obs, w1, b1);
    expert_fc2_kernel<<<dim3(1, 16, 16), 256>>>(w2);
    combine_kernel<<<(O_DIM * A_DIM + 255) / 256, 256>>>(b2, out);
}

// round 6
// speedup vs baseline: 1.3297x; 1.3297x over previous
#include <cuda_runtime.h>
#include <math.h>
#include <stdint.h>

#define O_DIM 1024
#define D_DIM 1024
#define E_NUM 16
#define TOPK  4
#define H_DIM 2048
#define A_DIM 64
#define NPAIR (O_DIM * TOPK)
#define FLT_MIN_NORM 1.17549435e-38f

// ---------------- scratch (static device memory; no allocs) ----------------
__device__ int   g_topk_idx[NPAIR];
__device__ float g_topk_gate[NPAIR];
__device__ float g_importance[O_DIM];
__device__ float g_load[O_DIM];
__device__ int   g_base[E_NUM + 1];
__device__ int   g_rows_sorted[NPAIR];
__device__ int   g_pair_of[NPAIR];
__device__ float g_h[NPAIR * H_DIM];   // 32 MB relu(fc1) activations
__device__ float g_z[NPAIR * A_DIM];   // 1 MB  fc2 outputs per pair

// ---------------- helpers ----------------
__device__ __forceinline__ unsigned f2tf(float x) {
    unsigned u;
    asm("cvt.rna.tf32.f32 %0, %1;" : "=r"(u) : "f"(x));
    return u;
}

__device__ __forceinline__ uint32_t smem_u32(const void* p) {
    uint32_t a;
    asm("{ .reg .u64 t; cvta.to.shared.u64 t, %1; cvt.u32.u64 %0, t; }" : "=r"(a) : "l"(p));
    return a;
}

__device__ __forceinline__ void cp_async16(uint32_t saddr, const void* gptr) {
    asm volatile("cp.async.cg.shared.global [%0], [%1], 16;" :: "r"(saddr), "l"(gptr));
}
__device__ __forceinline__ void cp_commit() {
    asm volatile("cp.async.commit_group;" ::: "memory");
}
template <int N> __device__ __forceinline__ void cp_wait() {
    asm volatile("cp.async.wait_group %0;" :: "n"(N) : "memory");
}

__device__ __forceinline__ void mma_tf32(float c[4], unsigned a0, unsigned a1,
                                         unsigned a2, unsigned a3,
                                         unsigned b0, unsigned b1) {
    asm volatile(
        "mma.sync.aligned.m16n8k8.row.col.f32.tf32.tf32.f32 "
        "{%0,%1,%2,%3}, {%4,%5,%6,%7}, {%8,%9}, {%0,%1,%2,%3};\n"
        : "+f"(c[0]), "+f"(c[1]), "+f"(c[2]), "+f"(c[3])
        : "r"(a0), "r"(a1), "r"(a2), "r"(a3), "r"(b0), "r"(b1));
}

// ---------------- K1: gating ----------------
__global__ __launch_bounds__(256) void gate_kernel(const float* __restrict__ obs,
                                                   const float* __restrict__ wg) {
    int o = blockIdx.x;
    int tid = threadIdx.x;
    const float* wrow = wg + (size_t)o * D_DIM * E_NUM;
    const float* orow = obs + (size_t)o * D_DIM;

    float acc[E_NUM];
#pragma unroll
    for (int i = 0; i < E_NUM; i++) acc[i] = 0.f;

    for (int d = tid; d < D_DIM; d += 256) {
        float x = orow[d];
        const float4* p = reinterpret_cast<const float4*>(wrow + (size_t)d * E_NUM);
        float4 v0 = p[0], v1 = p[1], v2 = p[2], v3 = p[3];
        acc[0]  += x * v0.x; acc[1]  += x * v0.y; acc[2]  += x * v0.z; acc[3]  += x * v0.w;
        acc[4]  += x * v1.x; acc[5]  += x * v1.y; acc[6]  += x * v1.z; acc[7]  += x * v1.w;
        acc[8]  += x * v2.x; acc[9]  += x * v2.y; acc[10] += x * v2.z; acc[11] += x * v2.w;
        acc[12] += x * v3.x; acc[13] += x * v3.y; acc[14] += x * v3.z; acc[15] += x * v3.w;
    }
#pragma unroll
    for (int i = 0; i < E_NUM; i++) {
#pragma unroll
        for (int off = 16; off; off >>= 1)
            acc[i] += __shfl_xor_sync(0xffffffffu, acc[i], off);
    }
    __shared__ float s[8][E_NUM];
    int warp = tid >> 5, lane = tid & 31;
    if (lane == 0) {
#pragma unroll
        for (int i = 0; i < E_NUM; i++) s[warp][i] = acc[i];
    }
    __syncthreads();
    if (tid == 0) {
        float logit[E_NUM];
        for (int e = 0; e < E_NUM; e++) {
            float t = 0.f;
            for (int w = 0; w < 8; w++) t += s[w][e];
            logit[e] = t;
        }
        bool taken[E_NUM];
        for (int e = 0; e < E_NUM; e++) taken[e] = false;
        int idx[TOPK]; float val[TOPK];
        for (int k = 0; k < TOPK; k++) {
            float best = -3.4e38f; int bi = 0;
            for (int e = 0; e < E_NUM; e++)
                if (!taken[e] && logit[e] > best) { best = logit[e]; bi = e; }
            taken[bi] = true; idx[k] = bi; val[k] = best;
        }
        float m = val[0];
        float ex[TOPK]; float se = 0.f;
        for (int k = 0; k < TOPK; k++) { ex[k] = expf(val[k] - m); se += ex[k]; }
        float gates[E_NUM];
        for (int e = 0; e < E_NUM; e++) gates[e] = 0.f;
        for (int k = 0; k < TOPK; k++) gates[idx[k]] = ex[k] / se;
        float imp = 0.f; int ldc = 0;
        for (int e = 0; e < E_NUM; e++) { imp += gates[e]; ldc += (gates[e] > 0.f); }
        for (int k = 0; k < TOPK; k++) {
            g_topk_idx[o * TOPK + k]  = idx[k];
            g_topk_gate[o * TOPK + k] = gates[idx[k]];
        }
        g_importance[o] = imp;
        g_load[o] = (float)ldc;
    }
}

// ---------------- K2: deterministic binning ----------------
__global__ __launch_bounds__(512) void bin_kernel() {
    int tid = threadIdx.x;
    int warp = tid >> 5, lane = tid & 31;
    int e = warp;
    __shared__ int scnt[E_NUM];
    __shared__ int sbase[E_NUM + 1];

    int cnt = 0;
    for (int base = 0; base < O_DIM; base += 32) {
        int r = base + lane;
        bool f = (g_topk_idx[r * 4 + 0] == e) || (g_topk_idx[r * 4 + 1] == e) ||
                 (g_topk_idx[r * 4 + 2] == e) || (g_topk_idx[r * 4 + 3] == e);
        unsigned m = __ballot_sync(0xffffffffu, f);
        cnt += __popc(m);
    }
    if (lane == 0) scnt[e] = cnt;
    __syncthreads();
    if (tid == 0) {
        int s = 0;
        for (int q = 0; q < E_NUM; q++) { sbase[q] = s; s += scnt[q]; }
        sbase[E_NUM] = s;
    }
    __syncthreads();
    if (tid < E_NUM + 1) g_base[tid] = sbase[tid];

    int off = sbase[e];
    for (int base = 0; base < O_DIM; base += 32) {
        int r = base + lane;
        int j = -1;
        if      (g_topk_idx[r * 4 + 0] == e) j = 0;
        else if (g_topk_idx[r * 4 + 1] == e) j = 1;
        else if (g_topk_idx[r * 4 + 2] == e) j = 2;
        else if (g_topk_idx[r * 4 + 3] == e) j = 3;
        bool f = (j >= 0);
        unsigned m = __ballot_sync(0xffffffffu, f);
        int pos = off + __popc(m & ((1u << lane) - 1u));
        if (f) {
            g_rows_sorted[pos] = r;
            g_pair_of[r * 4 + j] = pos;
        }
        off += __popc(m);
    }
}

// ---------------- K3: loss (two-pass variance, ddof=1) ----------------
__global__ __launch_bounds__(1024) void loss_kernel(float* __restrict__ out) {
    int tid = threadIdx.x;
    __shared__ float sh[32];
    __shared__ float bc;
    float imp = g_importance[tid];
    float ld  = g_load[tid];

    auto reduceSum = [&](float v) -> float {
#pragma unroll
        for (int o2 = 16; o2; o2 >>= 1) v += __shfl_xor_sync(0xffffffffu, v, o2);
        if ((tid & 31) == 0) sh[tid >> 5] = v;
        __syncthreads();
        if (tid < 32) {
            float r = sh[tid];
#pragma unroll
            for (int o2 = 16; o2; o2 >>= 1) r += __shfl_xor_sync(0xffffffffu, r, o2);
            if (tid == 0) bc = r;
        }
        __syncthreads();
        float r = bc;
        __syncthreads();
        return r;
    };

    float si  = reduceSum(imp);
    float mi  = si / (float)O_DIM;
    float di  = imp - mi;
    float ssi = reduceSum(di * di);
    float sl  = reduceSum(ld);
    float ml  = sl / (float)O_DIM;
    float dl  = ld - ml;
    float ssl = reduceSum(dl * dl);
    if (tid == 0) {
        float vi = ssi / (float)(O_DIM - 1);
        float vl = ssl / (float)(O_DIM - 1);
        float loss = (vi / (mi * mi + 1e-10f) + vl / (ml * ml + 1e-10f)) * 0.01f;
        out[3 * O_DIM * A_DIM] = loss;
    }
}

// ---------------- K4: action head (float4 streaming; FTZ-emulated tail) ----
__global__ __launch_bounds__(512) void action_kernel(const float* __restrict__ obs,
                                                     const float* __restrict__ lastw,
                                                     const float* __restrict__ lastb,
                                                     float* __restrict__ out) {
    int o = blockIdx.x;
    int tid = threadIdx.x;
    int a4 = (tid & 15) * 4;
    int chunk = tid >> 4;

    __shared__ float obsS[D_DIM];
    obsS[tid]       = obs[(size_t)o * D_DIM + tid];
    obsS[tid + 512] = obs[(size_t)o * D_DIM + tid + 512];
    __syncthreads();

    const float* lw = lastw + (size_t)o * D_DIM * A_DIM + (size_t)chunk * 32 * A_DIM + a4;
    float ax = 0.f, ay = 0.f, az = 0.f, aw = 0.f;
#pragma unroll 8
    for (int d = 0; d < 32; d++) {
        float4 w = *reinterpret_cast<const float4*>(lw + (size_t)d * A_DIM);
        float x = obsS[chunk * 32 + d];
        ax += x * w.x; ay += x * w.y; az += x * w.z; aw += x * w.w;
    }

    __shared__ float red[32][A_DIM];
    red[chunk][a4 + 0] = ax;
    red[chunk][a4 + 1] = ay;
    red[chunk][a4 + 2] = az;
    red[chunk][a4 + 3] = aw;
    __syncthreads();

    __shared__ float muS[A_DIM];
    __shared__ float eS[A_DIM];
    if (tid < A_DIM) {
        float m = 0.f;
        for (int c = 0; c < 32; c++) m += red[c][tid];
        muS[tid] = m + lastb[o * A_DIM + tid];
    }
    __syncthreads();
    if (tid < A_DIM) {
        float mx = muS[0];
        for (int i = 1; i < A_DIM; i++) mx = fmaxf(mx, muS[i]);
        float t  = muS[tid] - mx;
        float ef = expf(t);
        if (ef < FLT_MIN_NORM) ef = 0.f;          // FTZ: flush denormal exp result
        eS[tid] = ef;
    }
    __syncthreads();
    if (tid < A_DIM) {
        float ssum = 0.f;
        for (int i = 0; i < A_DIM; i++) ssum += eS[i];
        float p = eS[tid] / ssum;
        if (p < FLT_MIN_NORM) p = 0.f;            // FTZ: flush denormal quotient
        out[(size_t)o * A_DIM + tid] = p;
        float lp = (p == 0.f) ? logf(1e-8f) : logf(p);
        out[(size_t)O_DIM * A_DIM + o * A_DIM + tid] = lp;
    }
}

// ---------------- K5: fc1 grouped GEMM (tf32 mma + cp.async 3-stage) -------
// CTA 128M x 128N, 8 warps (2x4), warp tile 64x32, K-chunk 32.
// cp.async stages raw fp32 into a 3-buffer smem ring; cvt.rna applied on
// fragments after LDS. One __syncthreads per chunk (wait -> sync -> issue ->
// compute ordering makes the trailing barrier unnecessary).
#define FC1_A_STRIDE 36
#define FC1_B_STRIDE 136
#define FC1_A_FLOATS (128 * FC1_A_STRIDE)                 // 4608
#define FC1_B_FLOATS (32 * FC1_B_STRIDE)                  // 4352
#define FC1_STAGE    (FC1_A_FLOATS + FC1_B_FLOATS)        // 8960 floats
#define FC1_SMEM_BYTES (3 * FC1_STAGE * 4)                // 107520 B
#define FC1_NCHUNK  (D_DIM / 32)                          // 32

__global__ __launch_bounds__(256, 2) void expert_fc1_kernel(const float* __restrict__ obs,
                                                            const float* __restrict__ w1,
                                                            const float* __restrict__ b1) {
    int e = blockIdx.z, mt = blockIdx.y, nt = blockIdx.x;
    int pb = g_base[e];
    int ne = g_base[e + 1] - pb;
    int m0 = mt * 128;
    if (m0 >= ne) return;

    extern __shared__ float smem[];
    int tid = threadIdx.x;
    int lane = tid & 31, warp = tid >> 5;
    int wm = warp >> 2, wn = warp & 3;

    // per-thread load coordinates (fixed across chunks)
    int arow = tid >> 1;                      // 0..127
    int acol = (tid & 1) * 16;                // 0 or 16 (16 floats per thread)
    int mi = m0 + arow;
    int rowidx = g_rows_sorted[pb + (mi < ne ? mi : ne - 1)];
    const float* aptr = obs + (size_t)rowidx * D_DIM + acol;

    int bk = tid >> 3;                        // 0..31
    int bn = (tid & 7) * 16;                  // 0..112 (16 floats per thread)
    const float* bptr = w1 + (size_t)e * D_DIM * H_DIM + (size_t)nt * 128 +
                        (size_t)bk * H_DIM + bn;

    uint32_t sbase = smem_u32(smem);
    uint32_t aw_off = (uint32_t)(arow * FC1_A_STRIDE + acol) * 4;
    uint32_t bw_off = (uint32_t)(FC1_A_FLOATS + bk * FC1_B_STRIDE + bn) * 4;

    auto issue = [&](int st, int ch) {
        uint32_t sa = sbase + (uint32_t)(st * FC1_STAGE) * 4 + aw_off;
        const float* ag = aptr + ch * 32;
#pragma unroll
        for (int q = 0; q < 4; q++) cp_async16(sa + q * 16, ag + q * 4);
        uint32_t sb2 = sbase + (uint32_t)(st * FC1_STAGE) * 4 + bw_off;
        const float* bg = bptr + (size_t)ch * 32 * H_DIM;
#pragma unroll
        for (int q = 0; q < 4; q++) cp_async16(sb2 + q * 16, bg + q * 4);
        cp_commit();
    };

    float c[4][4][4];
#pragma unroll
    for (int i = 0; i < 4; i++)
#pragma unroll
        for (int j = 0; j < 4; j++)
#pragma unroll
            for (int q = 0; q < 4; q++) c[i][j][q] = 0.f;

    issue(0, 0);
    issue(1, 1);

    for (int ch = 0; ch < FC1_NCHUNK; ch++) {
        if (ch < FC1_NCHUNK - 2) cp_wait<1>(); else cp_wait<0>();
        __syncthreads();
        if (ch + 2 < FC1_NCHUNK) issue((ch + 2) % 3, ch + 2);

        const float* As = smem + (ch % 3) * FC1_STAGE;
        const float* Bs = As + FC1_A_FLOATS;

#pragma unroll
        for (int ks = 0; ks < 4; ks++) {
            int k8 = ks * 8;
            unsigned af[4][4], bf[4][2];
#pragma unroll
            for (int i = 0; i < 4; i++) {
                int r0 = wm * 64 + i * 16 + (lane >> 2);
                int kk = k8 + (lane & 3);
                af[i][0] = f2tf(As[r0 * FC1_A_STRIDE + kk]);
                af[i][1] = f2tf(As[(r0 + 8) * FC1_A_STRIDE + kk]);
                af[i][2] = f2tf(As[r0 * FC1_A_STRIDE + kk + 4]);
                af[i][3] = f2tf(As[(r0 + 8) * FC1_A_STRIDE + kk + 4]);
            }
#pragma unroll
            for (int j = 0; j < 4; j++) {
                int col = wn * 32 + j * 8 + (lane >> 2);
                bf[j][0] = f2tf(Bs[(k8 + (lane & 3)) * FC1_B_STRIDE + col]);
                bf[j][1] = f2tf(Bs[(k8 + (lane & 3) + 4) * FC1_B_STRIDE + col]);
            }
#pragma unroll
            for (int i = 0; i < 4; i++)
#pragma unroll
                for (int j = 0; j < 4; j++)
                    mma_tf32(c[i][j], af[i][0], af[i][1], af[i][2], af[i][3],
                             bf[j][0], bf[j][1]);
        }
    }

    // epilogue: bias + relu
    const float* b1e = b1 + e * H_DIM + nt * 128;
#pragma unroll
    for (int i = 0; i < 4; i++) {
        int r0 = m0 + wm * 64 + i * 16 + (lane >> 2);
#pragma unroll
        for (int j = 0; j < 4; j++) {
            int cc = wn * 32 + j * 8 + 2 * (lane & 3);
            float bv0 = b1e[cc], bv1 = b1e[cc + 1];
            if (r0 < ne) {
                float* dst = g_h + (size_t)(pb + r0) * H_DIM + nt * 128 + cc;
                dst[0] = fmaxf(c[i][j][0] + bv0, 0.f);
                dst[1] = fmaxf(c[i][j][1] + bv1, 0.f);
            }
            if (r0 + 8 < ne) {
                float* dst = g_h + (size_t)(pb + r0 + 8) * H_DIM + nt * 128 + cc;
                dst[0] = fmaxf(c[i][j][2] + bv0, 0.f);
                dst[1] = fmaxf(c[i][j][3] + bv1, 0.f);
            }
        }
    }
}

// ---------------- K6: grouped GEMM fc2 (h @ w2[e]) ----------------
__global__ __launch_bounds__(256) void expert_fc2_kernel(const float* __restrict__ w2) {
    int e = blockIdx.z, mt = blockIdx.y;
    int pb = g_base[e];
    int ne = g_base[e + 1] - pb;
    int m0 = mt * 64;
    if (m0 >= ne) return;

    __shared__ unsigned As[64][40];
    __shared__ unsigned Bs[32][72];

    int tid = threadIdx.x;
    int lane = tid & 31, warp = tid >> 5;
    int wm = warp >> 2, wn = warp & 3;

    float c[2][2][4];
#pragma unroll
    for (int i = 0; i < 2; i++)
#pragma unroll
        for (int j = 0; j < 2; j++)
#pragma unroll
            for (int q = 0; q < 4; q++) c[i][j][q] = 0.f;

    const float* w2e = w2 + (size_t)e * H_DIM * A_DIM;

    for (int kb = 0; kb < H_DIM; kb += 32) {
#pragma unroll
        for (int i = 0; i < 2; i++) {
            int v = tid + i * 256;
            int r = v >> 3, seg = v & 7;
            int row = pb + m0 + r;
            if (row > NPAIR - 1) row = NPAIR - 1;
            const float4* src = reinterpret_cast<const float4*>(
                g_h + (size_t)row * H_DIM + kb + seg * 4);
            float4 f = *src;
            As[r][seg * 4 + 0] = f2tf(f.x);
            As[r][seg * 4 + 1] = f2tf(f.y);
            As[r][seg * 4 + 2] = f2tf(f.z);
            As[r][seg * 4 + 3] = f2tf(f.w);
        }
#pragma unroll
        for (int i = 0; i < 2; i++) {
            int v = tid + i * 256;
            int k = v >> 4, seg = v & 15;
            const float4* src = reinterpret_cast<const float4*>(
                w2e + (size_t)(kb + k) * A_DIM + seg * 4);
            float4 f = *src;
            Bs[k][seg * 4 + 0] = f2tf(f.x);
            Bs[k][seg * 4 + 1] = f2tf(f.y);
            Bs[k][seg * 4 + 2] = f2tf(f.z);
            Bs[k][seg * 4 + 3] = f2tf(f.w);
        }
        __syncthreads();
#pragma unroll
        for (int ks = 0; ks < 4; ks++) {
            int k8 = ks * 8;
            unsigned af[2][4], bf[2][2];
#pragma unroll
            for (int i = 0; i < 2; i++) {
                int r0 = wm * 32 + i * 16 + (lane >> 2);
                int kk = k8 + (lane & 3);
                af[i][0] = As[r0][kk];
                af[i][1] = As[r0 + 8][kk];
                af[i][2] = As[r0][kk + 4];
                af[i][3] = As[r0 + 8][kk + 4];
            }
#pragma unroll
            for (int j = 0; j < 2; j++) {
                int col = wn * 16 + j * 8 + (lane >> 2);
                bf[j][0] = Bs[k8 + (lane & 3)][col];
                bf[j][1] = Bs[k8 + (lane & 3) + 4][col];
            }
#pragma unroll
            for (int i = 0; i < 2; i++)
#pragma unroll
                for (int j = 0; j < 2; j++)
                    mma_tf32(c[i][j], af[i][0], af[i][1], af[i][2], af[i][3],
                             bf[j][0], bf[j][1]);
        }
        __syncthreads();
    }

#pragma unroll
    for (int i = 0; i < 2; i++) {
        int r0 = m0 + wm * 32 + i * 16 + (lane >> 2);
#pragma unroll
        for (int j = 0; j < 2; j++) {
            int c0 = wn * 16 + j * 8 + 2 * (lane & 3);
            if (r0 < ne) {
                float* dst = g_z + (size_t)(pb + r0) * A_DIM + c0;
                dst[0] = c[i][j][0];
                dst[1] = c[i][j][1];
            }
            if (r0 + 8 < ne) {
                float* dst = g_z + (size_t)(pb + r0 + 8) * A_DIM + c0;
                dst[0] = c[i][j][2];
                dst[1] = c[i][j][3];
            }
        }
    }
}

// ---------------- K7: combine ----------------
__global__ __launch_bounds__(256) void combine_kernel(const float* __restrict__ b2,
                                                      float* __restrict__ out) {
    int i = blockIdx.x * blockDim.x + threadIdx.x;
    if (i >= O_DIM * A_DIM) return;
    int o = i >> 6, a = i & 63;
    float y = 0.f;
#pragma unroll
    for (int j = 0; j < TOPK; j++) {
        int eidx = g_topk_idx[o * TOPK + j];
        float g  = g_topk_gate[o * TOPK + j];
        int p    = g_pair_of[o * TOPK + j];
        y += g * (g_z[(size_t)p * A_DIM + a] + b2[eidx * A_DIM + a]);
    }
    out[2 * O_DIM * A_DIM + i] = y;
}

// ---------------- launch ----------------------------------------------------
extern "C" void kernel_launch(void* const* d_in, const int* in_sizes, int n_in,
                              void* d_out, int out_size) {
    const float* obs   = (const float*)d_in[0];
    const float* wgate = (const float*)d_in[1];
    const float* w1    = (const float*)d_in[2];
    const float* b1    = (const float*)d_in[3];
    const float* w2    = (const float*)d_in[4];
    const float* b2    = (const float*)d_in[5];
    const float* lastw = (const float*)d_in[6];
    const float* lastb = (const float*)d_in[7];
    float* out = (float*)d_out;

    static int smem_set = 0;
    if (!smem_set) {
        cudaFuncSetAttribute(expert_fc1_kernel,
                             cudaFuncAttributeMaxDynamicSharedMemorySize, FC1_SMEM_BYTES);
        smem_set = 1;
    }

    gate_kernel<<<O_DIM, 256>>>(obs, wgate);
    bin_kernel<<<1, 512>>>();
    loss_kernel<<<1, 1024>>>(out);
    action_kernel<<<O_DIM, 512>>>(obs, lastw, lastb, out);
    expert_fc1_kernel<<<dim3(16, 8, 16), 256, FC1_SMEM_BYTES>>>(obs, w1, b1);
    expert_fc2_kernel<<<dim3(1, 16, 16), 256>>>(w2);
    combine_kernel<<<(O_DIM * A_DIM + 255) / 256, 256>>>(b2, out);
}